// round 15
// baseline (speedup 1.0000x reference)
#include <cuda_runtime.h>
#include <math.h>

#define NPTS    16384               // 8 * 2048 points per cloud
#define DIM     32                  // cells per axis
#define DIM2    (DIM * DIM)
#define NCELLS  (DIM * DIM * DIM)   // 32768
#define ORG     (-5.0f)
#define H       0.3125f
#define INVH    3.2f
#define SPAD    (NCELLS + 4)
#define GRID    296                 // 2 blocks/SM on 148 SMs; co-resident
#define TPB     256
#define SCPT    (NCELLS / TPB)      // 128 cells per scan thread

// INVARIANT: g_count all-zero on entry (zero-init at load; re-zeroed in scan).
__device__ float4   g_sorted[2][NPTS];
__device__ int      g_count [2][NCELLS];
__device__ int      g_start [2][SPAD];
__device__ int      g_cursor[2][NCELLS];
__device__ int      g_cellid[2][NPTS];
__device__ int      g_pending[2 * NPTS];
__device__ int      g_pcount;
__device__ unsigned g_barcnt;       // arrive counter (self-resetting)
__device__ unsigned g_bargen;       // generation (monotonic across replays)

__device__ __forceinline__ int cell_coord(float v) {
    int c = (int)floorf((v - ORG) * INVH);
    return min(DIM - 1, max(0, c));
}

__device__ __forceinline__ void grid_barrier() {
    __syncthreads();
    if (threadIdx.x == 0) {
        volatile unsigned* genp = &g_bargen;
        unsigned g = *genp;
        __threadfence();
        if (atomicAdd(&g_barcnt, 1u) == (unsigned)(gridDim.x - 1)) {
            g_barcnt = 0;
            __threadfence();
            atomicAdd(&g_bargen, 1u);   // release
        } else {
            while (*genp == g) __nanosleep(40);
        }
        __threadfence();                 // acquire
    }
    __syncthreads();
}

__device__ __forceinline__ void scan_q4(const float4* __restrict__ tgt,
                                        const int* __restrict__ cst,
                                        int c0, int sub,
                                        float qx, float qy, float qz,
                                        float& best2) {
    const int s = cst[c0];
    const int e = cst[c0 + 1];
    for (int p = s + sub; p < e; p += 4) {
        const float4 b = tgt[p];
        const float dx = qx - b.x;
        const float dy = qy - b.y;
        const float dz = qz - b.z;
        const float d2 = fmaf(dx, dx, fmaf(dy, dy, dz * dz));
        best2 = fminf(best2, d2);
    }
}

__global__ void __launch_bounds__(TPB)
fused_kernel(const float* __restrict__ pc1,
             const float* __restrict__ pc2,
             float* __restrict__ out) {
    const int tid = blockIdx.x * blockDim.x + threadIdx.x;
    const int nth = gridDim.x * blockDim.x;     // 75776
    const int lane = threadIdx.x & 31;
    const int wid  = threadIdx.x >> 5;

    // ---------------- P0: init (ordered before all sums by the barriers)
    if (tid == 0) { out[0] = 0.0f; g_pcount = 0; }

    // ---------------- P1: histogram
    for (int i = tid; i < 2 * NPTS; i += nth) {
        int c = (i >= NPTS) ? 1 : 0;
        int j = i - c * NPTS;
        const float* pc = c ? pc2 : pc1;
        float x = pc[3 * j + 0], y = pc[3 * j + 1], z = pc[3 * j + 2];
        int cell = (cell_coord(z) * DIM + cell_coord(y)) * DIM + cell_coord(x);
        g_cellid[c][j] = cell;
        atomicAdd(&g_count[c][cell], 1);
    }
    grid_barrier();

    // ---------------- P2: scan (blocks 0 and 1; one per cloud). Two-pass:
    // pass 1 sums own chunk, pass 2 re-reads counts, writes prefixes, zeros.
    if (blockIdx.x < 2) {
        const int c = blockIdx.x;
        const int t = threadIdx.x;
        __shared__ int wtot[TPB / 32];

        const int base = t * SCPT;
        int local = 0;
        #pragma unroll 8
        for (int i = 0; i < SCPT; ++i) local += g_count[c][base + i];

        int incl = local;
        #pragma unroll
        for (int off = 1; off < 32; off <<= 1) {
            int u = __shfl_up_sync(0xFFFFFFFFu, incl, off);
            if (lane >= off) incl += u;
        }
        if (lane == 31) wtot[wid] = incl;
        __syncthreads();
        if (wid == 0) {
            int s = (lane < TPB / 32) ? wtot[lane] : 0;
            #pragma unroll
            for (int off = 1; off < TPB / 32; off <<= 1) {
                int u = __shfl_up_sync(0xFFFFFFFFu, s, off);
                if (lane >= off) s += u;
            }
            if (lane < TPB / 32) wtot[lane] = s;
        }
        __syncthreads();

        int run = incl - local + ((wid > 0) ? wtot[wid - 1] : 0);
        #pragma unroll 8
        for (int i = 0; i < SCPT; ++i) {
            const int cell = base + i;
            const int cnt = g_count[c][cell];
            g_start [c][cell] = run;
            g_cursor[c][cell] = run;
            g_count [c][cell] = 0;        // restore all-zero invariant
            run += cnt;
        }
        if (t == TPB - 1) g_start[c][NCELLS] = NPTS;
    }
    grid_barrier();

    // ---------------- P3: scatter
    for (int i = tid; i < 2 * NPTS; i += nth) {
        int c = (i >= NPTS) ? 1 : 0;
        int j = i - c * NPTS;
        const float* pc = c ? pc2 : pc1;
        float x = pc[3 * j + 0], y = pc[3 * j + 1], z = pc[3 * j + 2];
        int cell = g_cellid[c][j];
        int pos = atomicAdd(&g_cursor[c][cell], 1);
        g_sorted[c][pos] = make_float4(x, y, z, 0.0f);
    }
    grid_barrier();

    // ---------------- P4: box(1) quad-cooperative query with slab culling
    float dsum = 0.0f;
    {
        const int sub = threadIdx.x & 3;
        const unsigned qmask = 0xFu << (threadIdx.x & 28);
        const int nquads = nth >> 2;              // 18944
        const int qd0 = tid >> 2;

        for (int gq = qd0; gq < 2 * NPTS; gq += nquads) {
            const int dir = gq >> 14;
            const int qi  = gq & (NPTS - 1);
            const int tc  = dir ^ 1;

            const float4 q = g_sorted[dir][qi];
            const int cx = cell_coord(q.x);
            const int cy = cell_coord(q.y);
            const int cz = cell_coord(q.z);
            const float fx = q.x - (ORG + (float)cx * H);
            const float fy = q.y - (ORG + (float)cy * H);
            const float fz = q.z - (ORG + (float)cz * H);
            const float mfr = fmaxf(0.0f,
                fminf(fminf(fminf(fx, H - fx), fminf(fy, H - fy)),
                      fminf(fz, H - fz)));

            const float4* __restrict__ tgt = g_sorted[tc];
            const int*    __restrict__ cst = g_start[tc];

            float best2 = 3.0e38f;

            // Own cell -> quad-uniform gate.
            const int cc = (cz * DIM + cy) * DIM + cx;
            scan_q4(tgt, cst, cc, sub, q.x, q.y, q.z, best2);
            best2 = fminf(best2, __shfl_xor_sync(qmask, best2, 1));
            best2 = fminf(best2, __shfl_xor_sync(qmask, best2, 2));

            // 26 neighbors, slab-culled.
            {
                const float gate = best2;
                const float sx2[3] = { fx * fx, 0.0f, (H - fx) * (H - fx) };
                const float sy2[3] = { fy * fy, 0.0f, (H - fy) * (H - fy) };
                const float sz2[3] = { fz * fz, 0.0f, (H - fz) * (H - fz) };
                const bool okx[3] = { cx > 0, true, cx < DIM - 1 };
                const bool oky[3] = { cy > 0, true, cy < DIM - 1 };
                const bool okz[3] = { cz > 0, true, cz < DIM - 1 };

                #pragma unroll
                for (int iz = 0; iz < 3; ++iz) {
                    if (!okz[iz]) continue;
                    const float rz = sz2[iz];
                    if (rz >= gate) continue;
                    #pragma unroll
                    for (int iy = 0; iy < 3; ++iy) {
                        if (!oky[iy]) continue;
                        const float rzy = rz + sy2[iy];
                        if (rzy >= gate) continue;
                        const int rb = (cz + iz - 1) * DIM2
                                     + (cy + iy - 1) * DIM + cx;
                        #pragma unroll
                        for (int ix = 0; ix < 3; ++ix) {
                            if (iz == 1 && iy == 1 && ix == 1) continue;
                            if (!okx[ix]) continue;
                            if (rzy + sx2[ix] >= gate) continue;
                            scan_q4(tgt, cst, rb + ix - 1, sub,
                                    q.x, q.y, q.z, best2);
                        }
                    }
                }
                best2 = fminf(best2, __shfl_xor_sync(qmask, best2, 1));
                best2 = fminf(best2, __shfl_xor_sync(qmask, best2, 2));
            }

            const float bound = H + mfr;
            if (sub == 0) {
                if (best2 <= bound * bound) {
                    dsum += sqrtf(fmaxf(best2, 0.0f));
                } else {
                    int idx = atomicAdd(&g_pcount, 1);
                    g_pending[idx] = gq;
                }
            }
        }
    }
    grid_barrier();

    // ---------------- P5: warp-per-query brute force for pending
    {
        const int gwarp = tid >> 5;
        const int nwarp = nth >> 5;
        const int n = g_pcount;
        for (int w = gwarp; w < n; w += nwarp) {
            const int gq  = g_pending[w];
            const int dir = gq >> 14;
            const int qi  = gq & (NPTS - 1);
            const float4 q = g_sorted[dir][qi];
            const float4* __restrict__ tgt = g_sorted[dir ^ 1];

            float best2 = 3.0e38f;
            for (int p = lane; p < NPTS; p += 32) {
                const float4 b = tgt[p];
                const float dx = q.x - b.x;
                const float dy = q.y - b.y;
                const float dz = q.z - b.z;
                const float d2 = fmaf(dx, dx, fmaf(dy, dy, dz * dz));
                best2 = fminf(best2, d2);
            }
            #pragma unroll
            for (int off = 16; off > 0; off >>= 1)
                best2 = fminf(best2, __shfl_xor_sync(0xFFFFFFFFu, best2, off));
            if (lane == 0) dsum += sqrtf(fmaxf(best2, 0.0f));
        }
    }

    // ---------------- Final: block-reduce dsum, one atomicAdd per block.
    __shared__ float warp_sums[TPB / 32];
    float v = dsum;
    #pragma unroll
    for (int off = 16; off > 0; off >>= 1)
        v += __shfl_xor_sync(0xFFFFFFFFu, v, off);
    if (lane == 0) warp_sums[wid] = v;
    __syncthreads();
    if (threadIdx.x < 32) {
        float s = (lane < TPB / 32) ? warp_sums[lane] : 0.0f;
        #pragma unroll
        for (int off = (TPB / 64); off > 0; off >>= 1)
            s += __shfl_xor_sync(0xFFFFFFFFu, s, off);
        if (lane == 0 && s != 0.0f)
            atomicAdd(out, s * (1.0f / (float)NPTS));
    }
}

extern "C" void kernel_launch(void* const* d_in, const int* in_sizes, int n_in,
                              void* d_out, int out_size) {
    const float* pc1 = (const float*)d_in[0];
    const float* pc2 = (const float*)d_in[1];
    float* out = (float*)d_out;

    fused_kernel<<<GRID, TPB>>>(pc1, pc2, out);
}

// round 16
// speedup vs baseline: 2.8595x; 2.8595x over previous
#include <cuda_runtime.h>
#include <math.h>

#define NPTS    16384               // 8 * 2048 points per cloud
#define DIM     32
#define DIM2    (DIM * DIM)
#define NCELLS  (DIM * DIM * DIM)   // 32768
#define TOTC    (2 * NCELLS)        // 65536 (flattened, both clouds)
#define ORG     (-5.0f)
#define H       0.3125f
#define INVH    3.2f
#define GRID    512                 // 4 blocks/SM cap -> single co-resident wave
#define TPB     256

// INVARIANT: g_count all-zero on entry (zero-init at load; re-zeroed in scan).
__device__ float4   g_sorted[2 * NPTS];     // flat: cloud0 then cloud1
__device__ int      g_count [TOTC];
__device__ int      g_start [TOTC + 8];     // [TOTC] = sentinel (2*NPTS)
__device__ int      g_cursor[TOTC];
__device__ int      g_cellid[2 * NPTS];
__device__ int      g_bsum[256];            // per-block scan sums
__device__ int      g_boff[256];            // exclusive block offsets
__device__ int      g_pending[2 * NPTS];
__device__ int      g_pcount;
__device__ unsigned g_barcnt;
__device__ unsigned g_bargen;               // monotonic across replays

__device__ __forceinline__ int cell_coord(float v) {
    int c = (int)floorf((v - ORG) * INVH);
    return min(DIM - 1, max(0, c));
}

__device__ __forceinline__ void grid_barrier() {
    __syncthreads();
    if (threadIdx.x == 0) {
        volatile unsigned* genp = &g_bargen;
        unsigned g = *genp;
        __threadfence();
        if (atomicAdd(&g_barcnt, 1u) == (unsigned)(gridDim.x - 1)) {
            g_barcnt = 0;
            __threadfence();
            atomicAdd(&g_bargen, 1u);       // release
        } else {
            while (*genp == g) __nanosleep(64);
        }
        __threadfence();                    // acquire
    }
    __syncthreads();
}

// Block-wide exclusive scan of one int per thread (256 threads).
// Returns exclusive prefix; *total gets the block total (valid in all threads).
__device__ __forceinline__ int block_exscan(int v, int* smem32, int* total) {
    const int lane = threadIdx.x & 31;
    const int w    = threadIdx.x >> 5;
    int incl = v;
    #pragma unroll
    for (int off = 1; off < 32; off <<= 1) {
        int u = __shfl_up_sync(0xFFFFFFFFu, incl, off);
        if (lane >= off) incl += u;
    }
    if (lane == 31) smem32[w] = incl;
    __syncthreads();
    if (w == 0) {
        int s = (lane < 8) ? smem32[lane] : 0;
        #pragma unroll
        for (int off = 1; off < 8; off <<= 1) {
            int u = __shfl_up_sync(0xFFFFFFFFu, s, off);
            if (lane >= off) s += u;
        }
        if (lane < 8) smem32[lane] = s;
    }
    __syncthreads();
    int woff = (w > 0) ? smem32[w - 1] : 0;
    *total = smem32[7];
    __syncthreads();
    return incl - v + woff;
}

__device__ __forceinline__ void scan_q4(const float4* __restrict__ tgt,
                                        const int* __restrict__ cst,
                                        int c0, int sub,
                                        float qx, float qy, float qz,
                                        float& best2) {
    const int s = cst[c0];
    const int e = cst[c0 + 1];
    for (int p = s + sub; p < e; p += 4) {
        const float4 b = tgt[p];
        const float dx = qx - b.x;
        const float dy = qy - b.y;
        const float dz = qz - b.z;
        const float d2 = fmaf(dx, dx, fmaf(dy, dy, dz * dz));
        best2 = fminf(best2, d2);
    }
}

__global__ void __launch_bounds__(TPB, 4)
fused_kernel(const float* __restrict__ pc1,
             const float* __restrict__ pc2,
             float* __restrict__ out) {
    const int tid  = blockIdx.x * blockDim.x + threadIdx.x;   // 0 .. 131071
    const int lane = threadIdx.x & 31;
    const int wid  = threadIdx.x >> 5;
    __shared__ int sscan[32];

    // ---------------- P0: init
    if (tid == 0) { out[0] = 0.0f; g_pcount = 0; }

    // ---------------- P1: histogram (1 point per thread for tid < 32768)
    if (tid < 2 * NPTS) {
        int c = (tid >= NPTS) ? 1 : 0;
        int j = tid - c * NPTS;
        const float* pc = c ? pc2 : pc1;
        float x = pc[3 * j + 0], y = pc[3 * j + 1], z = pc[3 * j + 2];
        int cell = c * NCELLS
                 + (cell_coord(z) * DIM + cell_coord(y)) * DIM + cell_coord(x);
        g_cellid[tid] = cell;
        atomicAdd(&g_count[cell], 1);
    }
    grid_barrier();

    // ---------------- P2a: per-block scan of 256 cells (blocks 0..255)
    if (blockIdx.x < 256) {
        const int cell = blockIdx.x * TPB + threadIdx.x;
        const int cnt  = g_count[cell];
        int total;
        int ex = block_exscan(cnt, sscan, &total);
        g_start[cell] = ex;                   // partial (block-local) prefix
        if (threadIdx.x == 0) g_bsum[blockIdx.x] = total;
    }
    grid_barrier();

    // ---------------- P2b: block 256 scans the 256 block sums
    if (blockIdx.x == 256) {
        int v = g_bsum[threadIdx.x];
        int total;
        int ex = block_exscan(v, sscan, &total);
        g_boff[threadIdx.x] = ex;
    }
    grid_barrier();

    // ---------------- P2c: add offsets, write cursor, re-zero counts
    if (blockIdx.x < 256) {
        const int cell = blockIdx.x * TPB + threadIdx.x;
        const int v = g_start[cell] + g_boff[blockIdx.x];
        g_start [cell] = v;
        g_cursor[cell] = v;
        g_count [cell] = 0;                   // restore all-zero invariant
    }
    if (tid == 0) g_start[TOTC] = 2 * NPTS;   // sentinel
    grid_barrier();

    // ---------------- P3: scatter (flat positions)
    if (tid < 2 * NPTS) {
        int c = (tid >= NPTS) ? 1 : 0;
        int j = tid - c * NPTS;
        const float* pc = c ? pc2 : pc1;
        float x = pc[3 * j + 0], y = pc[3 * j + 1], z = pc[3 * j + 2];
        int pos = atomicAdd(&g_cursor[g_cellid[tid]], 1);
        g_sorted[pos] = make_float4(x, y, z, 0.0f);
    }
    grid_barrier();

    // ---------------- P4: box(1) quad-cooperative query w/ slab culling
    float dsum = 0.0f;
    {
        const int sub = threadIdx.x & 3;
        const unsigned qmask = 0xFu << (threadIdx.x & 28);
        const int gq  = tid >> 2;             // exactly one quad per query
        const int dir = gq >> 14;
        const int qi  = gq & (NPTS - 1);
        const int tc  = dir ^ 1;

        const float4 q = g_sorted[g_start[dir * NCELLS] == 0 ? dir * NPTS + qi
                                                             : dir * NPTS + qi];
        const int cx = cell_coord(q.x);
        const int cy = cell_coord(q.y);
        const int cz = cell_coord(q.z);
        const float fx = q.x - (ORG + (float)cx * H);
        const float fy = q.y - (ORG + (float)cy * H);
        const float fz = q.z - (ORG + (float)cz * H);
        const float mfr = fmaxf(0.0f,
            fminf(fminf(fminf(fx, H - fx), fminf(fy, H - fy)),
                  fminf(fz, H - fz)));

        const float4* __restrict__ tgt = g_sorted;        // flat
        const int*    __restrict__ cst = g_start + tc * NCELLS;

        float best2 = 3.0e38f;

        const int cc = (cz * DIM + cy) * DIM + cx;
        scan_q4(tgt, cst, cc, sub, q.x, q.y, q.z, best2);
        best2 = fminf(best2, __shfl_xor_sync(qmask, best2, 1));
        best2 = fminf(best2, __shfl_xor_sync(qmask, best2, 2));

        {
            const float gate = best2;
            const float sx2[3] = { fx * fx, 0.0f, (H - fx) * (H - fx) };
            const float sy2[3] = { fy * fy, 0.0f, (H - fy) * (H - fy) };
            const float sz2[3] = { fz * fz, 0.0f, (H - fz) * (H - fz) };
            const bool okx[3] = { cx > 0, true, cx < DIM - 1 };
            const bool oky[3] = { cy > 0, true, cy < DIM - 1 };
            const bool okz[3] = { cz > 0, true, cz < DIM - 1 };

            #pragma unroll
            for (int iz = 0; iz < 3; ++iz) {
                if (!okz[iz]) continue;
                const float rz = sz2[iz];
                if (rz >= gate) continue;
                #pragma unroll
                for (int iy = 0; iy < 3; ++iy) {
                    if (!oky[iy]) continue;
                    const float rzy = rz + sy2[iy];
                    if (rzy >= gate) continue;
                    const int rb = (cz + iz - 1) * DIM2 + (cy + iy - 1) * DIM + cx;
                    #pragma unroll
                    for (int ix = 0; ix < 3; ++ix) {
                        if (iz == 1 && iy == 1 && ix == 1) continue;
                        if (!okx[ix]) continue;
                        if (rzy + sx2[ix] >= gate) continue;
                        scan_q4(tgt, cst, rb + ix - 1, sub,
                                q.x, q.y, q.z, best2);
                    }
                }
            }
            best2 = fminf(best2, __shfl_xor_sync(qmask, best2, 1));
            best2 = fminf(best2, __shfl_xor_sync(qmask, best2, 2));
        }

        const float bound = H + mfr;
        if (sub == 0) {
            if (best2 <= bound * bound) {
                dsum += sqrtf(fmaxf(best2, 0.0f));
            } else {
                int idx = atomicAdd(&g_pcount, 1);
                g_pending[idx] = gq;
            }
        }
    }
    grid_barrier();

    // ---------------- P5: warp-per-query brute force for pending
    {
        const int gwarp = tid >> 5;
        const int nwarp = (GRID * TPB) >> 5;              // 4096
        const int n = g_pcount;
        for (int w = gwarp; w < n; w += nwarp) {
            const int gq  = g_pending[w];
            const int dir = gq >> 14;
            const int qi  = gq & (NPTS - 1);
            const float4 q = g_sorted[dir * NPTS + qi];
            const float4* __restrict__ tgt = g_sorted + (dir ^ 1) * NPTS;

            float best2 = 3.0e38f;
            for (int p = lane; p < NPTS; p += 32) {
                const float4 b = tgt[p];
                const float dx = q.x - b.x;
                const float dy = q.y - b.y;
                const float dz = q.z - b.z;
                const float d2 = fmaf(dx, dx, fmaf(dy, dy, dz * dz));
                best2 = fminf(best2, d2);
            }
            #pragma unroll
            for (int off = 16; off > 0; off >>= 1)
                best2 = fminf(best2, __shfl_xor_sync(0xFFFFFFFFu, best2, off));
            if (lane == 0) dsum += sqrtf(fmaxf(best2, 0.0f));
        }
    }

    // ---------------- Final: block reduction, one atomicAdd per block.
    __shared__ float warp_sums[TPB / 32];
    float v = dsum;
    #pragma unroll
    for (int off = 16; off > 0; off >>= 1)
        v += __shfl_xor_sync(0xFFFFFFFFu, v, off);
    if (lane == 0) warp_sums[wid] = v;
    __syncthreads();
    if (threadIdx.x < 32) {
        float s = (lane < TPB / 32) ? warp_sums[lane] : 0.0f;
        #pragma unroll
        for (int off = (TPB / 64); off > 0; off >>= 1)
            s += __shfl_xor_sync(0xFFFFFFFFu, s, off);
        if (lane == 0 && s != 0.0f)
            atomicAdd(out, s * (1.0f / (float)NPTS));
    }
}

extern "C" void kernel_launch(void* const* d_in, const int* in_sizes, int n_in,
                              void* d_out, int out_size) {
    const float* pc1 = (const float*)d_in[0];
    const float* pc2 = (const float*)d_in[1];
    float* out = (float*)d_out;

    fused_kernel<<<GRID, TPB>>>(pc1, pc2, out);
}